// round 15
// baseline (speedup 1.0000x reference)
#include <cuda_runtime.h>
#include <cuda_bf16.h>
#include <math.h>
#include <stdint.h>

// ---------------- problem constants ----------------
#define BATCH 32
#define C1    2048
#define HW    1024
#define D1    1024
#define D2    256
#define NC    1000
#define BN_EPS 1e-5f
#define NORM_EPS 1e-12f

// ---------------- scratch ----------------
__device__ __nv_bfloat16 g_xh[(size_t)BATCH * HW * C1];  // xT bf16 [b,s,c]
__device__ __nv_bfloat16 g_w1[(size_t)D1 * C1];
__device__ __nv_bfloat16 g_w2hi[(size_t)D2 * D1];
__device__ __nv_bfloat16 g_w2lo[(size_t)D2 * D1];
__device__ __nv_bfloat16 g_hhi[(size_t)BATCH * HW * D1]; // hT bf16 hi [b,s,d]
__device__ __nv_bfloat16 g_hlo[(size_t)BATCH * HW * D1];
__device__ float g_bnsum[256 * D1];
__device__ float g_bnsq[256 * D1];
__device__ float g_scale[D1];
__device__ float g_shift[D1];
__device__ float g_part[BATCH * 16 * D2];                // per (b, s-block of 64)
__device__ float g_g[BATCH * D2];

// ---------------- low-level helpers ----------------
__device__ __forceinline__ uint32_t smem_u32(const void* p) {
    uint32_t a;
    asm("{ .reg .u64 t; cvta.to.shared.u64 t, %1; cvt.u32.u64 %0, t; }" : "=r"(a) : "l"(p));
    return a;
}
__device__ __forceinline__ void cpa16(uint32_t dst, const void* src) {
    asm volatile("cp.async.cg.shared.global [%0], [%1], 16;" :: "r"(dst), "l"(src));
}
#define CP_COMMIT() asm volatile("cp.async.commit_group;" ::: "memory")
#define CP_WAIT(n)  asm volatile("cp.async.wait_group %0;" :: "n"(n) : "memory")

__device__ __forceinline__ void ldsm4(uint32_t r[4], uint32_t a) {
    asm volatile("ldmatrix.sync.aligned.m8n8.x4.shared.b16 {%0,%1,%2,%3}, [%4];"
        : "=r"(r[0]), "=r"(r[1]), "=r"(r[2]), "=r"(r[3]) : "r"(a));
}
__device__ __forceinline__ void mma16816(float c[4], const uint32_t a[4], const uint32_t b[2]) {
    asm("mma.sync.aligned.m16n8k16.row.col.f32.bf16.bf16.f32 "
        "{%0,%1,%2,%3}, {%4,%5,%6,%7}, {%8,%9}, {%0,%1,%2,%3};"
        : "+f"(c[0]), "+f"(c[1]), "+f"(c[2]), "+f"(c[3])
        : "r"(a[0]), "r"(a[1]), "r"(a[2]), "r"(a[3]), "r"(b[0]), "r"(b[1]));
}
__device__ __forceinline__ float2 bf2f(uint32_t u) {
    return __bfloat1622float2(*reinterpret_cast<const __nv_bfloat162*>(&u));
}

// ---------------- tiling constants ----------------
// gemm1: KT=64 (128B rows + 16B pad = 144B; 36 words == 4 mod 32 -> conflict-free ldsm)
#define ROWB1   144
#define TILE1_B (128 * ROWB1)       // 18432
#define STAGE1_B (2 * TILE1_B)      // 36864 (A, B)
#define G1_SMEM  73728              // 2 stages; epilogue needs 68608
#define EPI_SUM   16640             // float offsets in gemm1 epilogue
#define EPI_SQ    16896
// gemm2: 80B rows; CTA 256(M) x 64(N)
#define ROWB   80
#define A2_TILE (256 * ROWB)        // 20480 per array
#define B2_TILE (64 * ROWB)         // 5120 per array
#define STAGE2_B (2 * A2_TILE + 2 * B2_TILE)   // 51200
#define G2_SMEM (2 * STAGE2_B)      // 102400
#define SMF2_PAD 66                 // EVEN: float2 stores stay 8B-aligned
#define EPI2_RED (256 * SMF2_PAD)   // float offset: red[4][64]
#define EPI2_INV (EPI2_RED + 256)   // float offset: inv[64]  (total 68864 B <= 102400)

// ================= convert kernels =================
__global__ __launch_bounds__(256) void convert_w1_kernel(
    const float* __restrict__ W, __nv_bfloat16* __restrict__ O, int n)
{
    int i = blockIdx.x * 256 + threadIdx.x;
    if (i < n) O[i] = __float2bfloat16(W[i]);
}

__global__ __launch_bounds__(256) void convert_w_kernel(
    const float* __restrict__ W, __nv_bfloat16* __restrict__ hi, __nv_bfloat16* __restrict__ lo, int n)
{
    int i = blockIdx.x * 256 + threadIdx.x;
    if (i < n) {
        float v = W[i];
        __nv_bfloat16 h = __float2bfloat16(v);
        hi[i] = h;
        lo[i] = __float2bfloat16(v - __bfloat162float(h));
    }
}

__global__ __launch_bounds__(256) void convert_x_kernel(
    const float* __restrict__ X, __nv_bfloat16* __restrict__ T)
{
    __shared__ float t[64][33];
    const int s0 = blockIdx.x * 32, c0 = blockIdx.y * 64, b = blockIdx.z;
    const float* xb = X + (size_t)b * C1 * HW;
#pragma unroll
    for (int it = 0; it < 8; it++) {
        int e = threadIdx.x + it * 256;
        int ci = e >> 5, sj = e & 31;
        t[ci][sj] = xb[(size_t)(c0 + ci) * HW + s0 + sj];
    }
    __syncthreads();
#pragma unroll
    for (int it = 0; it < 8; it++) {
        int e = threadIdx.x + it * 256;
        int sj = e >> 6, ci = e & 63;
        T[((size_t)b * HW + s0 + sj) * C1 + c0 + ci] = __float2bfloat16(t[ci][sj]);
    }
}

// ================= GEMM1: bf16 1-pass, KT=64, fused BN partials =================
__global__ __launch_bounds__(256, 2) void gemm1_mma(
    const __nv_bfloat16* __restrict__ A, const __nv_bfloat16* __restrict__ B,
    __nv_bfloat16* __restrict__ Hhi, __nv_bfloat16* __restrict__ Hlo)
{
    extern __shared__ char sm[];
    const uint32_t sb = smem_u32(sm);
    const int tid = threadIdx.x;
    const int lane = tid & 31, wid = tid >> 5;
    const int wm = wid & 3, wn = wid >> 2;
    const int b = blockIdx.z;
    const int tileM = blockIdx.y * 128;
    const int tileN = blockIdx.x * 128;

    const __nv_bfloat16* gA = A + (size_t)tileM * C1;
    const __nv_bfloat16* gB = B + ((size_t)b * HW + tileN) * C1;

    float acc[2][8][4];
#pragma unroll
    for (int i = 0; i < 2; i++)
#pragma unroll
        for (int j = 0; j < 8; j++)
#pragma unroll
            for (int q = 0; q < 4; q++) acc[i][j][q] = 0.f;

    const int lr = tid & 127;
    const int jbase = tid >> 7;
    const int a_row = wm * 32 + (lane & 15);
    const int a_k8  = (lane >> 4) << 3;
    const int b_row = wn * 64 + ((lane >> 4) << 3) + (lane & 7);
    const int b_k8  = ((lane >> 3) & 1) << 3;

    auto issue_stage = [&](int kt, int st) {
        const int k0 = kt * 64;
        const uint32_t s0 = sb + st * STAGE1_B;
#pragma unroll
        for (int it = 0; it < 4; it++) {
            int j = it * 2 + jbase;
            cpa16(s0 + lr * ROWB1 + j * 16,           gA + (size_t)lr * C1 + k0 + j * 8);
            cpa16(s0 + TILE1_B + lr * ROWB1 + j * 16, gB + (size_t)lr * C1 + k0 + j * 8);
        }
        CP_COMMIT();
    };

    const int NK = C1 / 64;   // 32
    issue_stage(0, 0);
    for (int kt = 0; kt < NK; kt++) {
        const int st = kt & 1;
        CP_WAIT(0);
        __syncthreads();
        if (kt + 1 < NK) issue_stage(kt + 1, st ^ 1);
        const uint32_t aS = sb + st * STAGE1_B;
        const uint32_t bS = aS + TILE1_B;
#pragma unroll
        for (int kk = 0; kk < 4; kk++) {
            const int akb = (kk * 16 + a_k8) * 2;
            const int bkb = (kk * 16 + b_k8) * 2;
            uint32_t a[2][4], bb[8][2];
#pragma unroll
            for (int i = 0; i < 2; i++)
                ldsm4(a[i], aS + (a_row + i * 16) * ROWB1 + akb);
#pragma unroll
            for (int q = 0; q < 4; q++) {
                uint32_t r4[4];
                ldsm4(r4, bS + (b_row + q * 16) * ROWB1 + bkb);
                bb[2*q][0] = r4[0]; bb[2*q][1] = r4[1];
                bb[2*q+1][0] = r4[2]; bb[2*q+1][1] = r4[3];
            }
#pragma unroll
            for (int i = 0; i < 2; i++)
#pragma unroll
                for (int j = 0; j < 8; j++) mma16816(acc[i][j], a[i], bb[j]);
        }
    }

    // epilogue: acc -> smem fp32 (pad 130, even)
    __syncthreads();
    float* smf = (float*)sm;
#pragma unroll
    for (int i = 0; i < 2; i++) {
        int m0 = wm * 32 + i * 16 + (lane >> 2);
#pragma unroll
        for (int j = 0; j < 8; j++) {
            int n0 = wn * 64 + j * 8 + (lane & 3) * 2;
            *(float2*)&smf[m0 * 130 + n0]       = make_float2(acc[i][j][0], acc[i][j][1]);
            *(float2*)&smf[(m0 + 8) * 130 + n0] = make_float2(acc[i][j][2], acc[i][j][3]);
        }
    }
    __syncthreads();

    // (a) transposed bf16 hi/lo out [b,s,d]
    {
        int s = tid & 127, half = tid >> 7;
        __nv_bfloat16* oh = Hhi + ((size_t)b * HW + tileN + s) * D1 + tileM + half * 64;
        __nv_bfloat16* ol = Hlo + ((size_t)b * HW + tileN + s) * D1 + tileM + half * 64;
#pragma unroll
        for (int c = 0; c < 8; c++) {
            __align__(16) __nv_bfloat16 ph[8], pl[8];
#pragma unroll
            for (int e = 0; e < 8; e++) {
                float v = smf[(half * 64 + c * 8 + e) * 130 + s];
                __nv_bfloat16 h = __float2bfloat16(v);
                ph[e] = h;
                pl[e] = __float2bfloat16(v - __bfloat162float(h));
            }
            *(uint4*)(oh + c * 8) = *(const uint4*)ph;
            *(uint4*)(ol + c * 8) = *(const uint4*)pl;
        }
    }

    // (b) fused BN partial stats
    {
        int dl = tid & 127, half = tid >> 7;
        float s = 0.f, q = 0.f;
        const float* row = &smf[dl * 130 + half * 64];
#pragma unroll 8
        for (int i = 0; i < 64; i++) {
            float v = row[i];
            s += v;
            q = fmaf(v, v, q);
        }
        smf[EPI_SUM + tid] = s;
        smf[EPI_SQ + tid]  = q;
        __syncthreads();
        if (half == 0) {
            float S = smf[EPI_SUM + dl] + smf[EPI_SUM + 128 + dl];
            float Q = smf[EPI_SQ + dl]  + smf[EPI_SQ + 128 + dl];
            int p = b * 8 + blockIdx.x;
            g_bnsum[p * D1 + tileM + dl] = S;
            g_bnsq[p * D1 + tileM + dl]  = Q;
        }
    }
}

// ================= BN reduce =================
__global__ __launch_bounds__(256) void bn_reduce_kernel(
    const float* __restrict__ gamma, const float* __restrict__ beta)
{
    int d = blockIdx.x * 256 + threadIdx.x;
    float s = 0.f, q = 0.f;
    for (int p = 0; p < 256; p++) { s += g_bnsum[p * D1 + d]; q += g_bnsq[p * D1 + d]; }
    const float invN = 1.f / (float)(BATCH * HW);
    float mean = s * invN;
    float var = fmaf(-mean, mean, q * invN);
    float sc = gamma[d] * rsqrtf(var + BN_EPS);
    g_scale[d] = sc;
    g_shift[d] = fmaf(-mean, sc, beta[d]);
}

// ================= GEMM2: CTA 256x64, bf16 3-pass, fused BN+ReLU, fused norm+sum =================
__global__ __launch_bounds__(256, 2) void gemm2_mma(
    const __nv_bfloat16* __restrict__ Ahi, const __nv_bfloat16* __restrict__ Alo,
    const __nv_bfloat16* __restrict__ Hhi, const __nv_bfloat16* __restrict__ Hlo)
{
    extern __shared__ char sm[];
    const uint32_t sb = smem_u32(sm);
    const int tid = threadIdx.x;
    const int lane = tid & 31, wid = tid >> 5;   // wid 0..7 = m-tile of 32
    const int b = blockIdx.z;
    const int tileN = blockIdx.x * 64;           // s-block

    float acc[2][8][4];
#pragma unroll
    for (int i = 0; i < 2; i++)
#pragma unroll
        for (int j = 0; j < 8; j++)
#pragma unroll
            for (int q = 0; q < 4; q++) acc[i][j][q] = 0.f;

    const int lrA = tid;                         // A row 0..255
    const int lrB = tid & 63;                    // B row
    const int jB  = tid >> 6;                    // B chunk 0..3
    const int a_row = wid * 32 + (lane & 15);
    const int a_k8  = (lane >> 4) << 3;
    const int b_row = ((lane >> 4) << 3) + (lane & 7);
    const int b_k8  = ((lane >> 3) & 1) << 3;

    uint4 rh, rl;

    auto issueA = [&](int kt, int st) {
        const int k0 = kt * 32;
        const uint32_t s0 = sb + st * STAGE2_B;
#pragma unroll
        for (int j = 0; j < 4; j++) {
            cpa16(s0 + lrA * ROWB + j * 16,           Ahi + (size_t)lrA * D1 + k0 + j * 8);
            cpa16(s0 + A2_TILE + lrA * ROWB + j * 16, Alo + (size_t)lrA * D1 + k0 + j * 8);
        }
        CP_COMMIT();
    };
    auto ldgB = [&](int kt) {
        const int k0 = kt * 32;
        size_t off = ((size_t)b * HW + tileN + lrB) * D1 + k0 + jB * 8;
        rh = *(const uint4*)(Hhi + off);
        rl = *(const uint4*)(Hlo + off);
    };
    auto stsB = [&](int kt, int st) {
        const int k0 = kt * 32;
        const uint32_t soff = st * STAGE2_B + 2 * A2_TILE;
        int d0 = k0 + jB * 8;
        float sc[8], sh[8];
        *(float4*)&sc[0] = *(const float4*)&g_scale[d0];
        *(float4*)&sc[4] = *(const float4*)&g_scale[d0 + 4];
        *(float4*)&sh[0] = *(const float4*)&g_shift[d0];
        *(float4*)&sh[4] = *(const float4*)&g_shift[d0 + 4];
        const uint32_t* ph = (const uint32_t*)&rh;
        const uint32_t* pl = (const uint32_t*)&rl;
        __align__(16) __nv_bfloat16 bh[8], bl[8];
#pragma unroll
        for (int w = 0; w < 4; w++) {
            float2 fh = bf2f(ph[w]);
            float2 fl = bf2f(pl[w]);
            float v0 = fh.x + fl.x, v1 = fh.y + fl.y;
            float u0 = fmaxf(fmaf(v0, sc[2*w],   sh[2*w]),   0.f);
            float u1 = fmaxf(fmaf(v1, sc[2*w+1], sh[2*w+1]), 0.f);
            __nv_bfloat16 h0 = __float2bfloat16(u0);
            __nv_bfloat16 h1 = __float2bfloat16(u1);
            bh[2*w] = h0;   bl[2*w]   = __float2bfloat16(u0 - __bfloat162float(h0));
            bh[2*w+1] = h1; bl[2*w+1] = __float2bfloat16(u1 - __bfloat162float(h1));
        }
        *(uint4*)(sm + soff + lrB * ROWB + jB * 16)           = *(const uint4*)bh;
        *(uint4*)(sm + soff + B2_TILE + lrB * ROWB + jB * 16) = *(const uint4*)bl;
    };

    const int NK = D1 / 32;   // 32
    issueA(0, 0);
    ldgB(0);
    stsB(0, 0);
    for (int kt = 0; kt < NK; kt++) {
        const int st = kt & 1;
        CP_WAIT(0);
        __syncthreads();
        if (kt + 1 < NK) { issueA(kt + 1, st ^ 1); ldgB(kt + 1); }
        const uint32_t s0 = sb + st * STAGE2_B;
        const uint32_t aHs = s0, aLs = s0 + A2_TILE;
        const uint32_t bHs = s0 + 2 * A2_TILE, bLs = bHs + B2_TILE;
#pragma unroll
        for (int kk = 0; kk < 2; kk++) {
            const int akb = (kk * 16 + a_k8) * 2;
            const int bkb = (kk * 16 + b_k8) * 2;
            uint32_t ah[2][4], al[2][4], bb[8][2];
#pragma unroll
            for (int i = 0; i < 2; i++)
                ldsm4(ah[i], aHs + (a_row + i * 16) * ROWB + akb);
#pragma unroll
            for (int q = 0; q < 4; q++) {
                uint32_t r4[4];
                ldsm4(r4, bHs + (b_row + q * 16) * ROWB + bkb);
                bb[2*q][0] = r4[0]; bb[2*q][1] = r4[1];
                bb[2*q+1][0] = r4[2]; bb[2*q+1][1] = r4[3];
            }
#pragma unroll
            for (int i = 0; i < 2; i++)
#pragma unroll
                for (int j = 0; j < 8; j++) mma16816(acc[i][j], ah[i], bb[j]);
#pragma unroll
            for (int i = 0; i < 2; i++)
                ldsm4(al[i], aLs + (a_row + i * 16) * ROWB + akb);
#pragma unroll
            for (int i = 0; i < 2; i++)
#pragma unroll
                for (int j = 0; j < 8; j++) mma16816(acc[i][j], al[i], bb[j]);
#pragma unroll
            for (int q = 0; q < 4; q++) {
                uint32_t r4[4];
                ldsm4(r4, bLs + (b_row + q * 16) * ROWB + bkb);
                bb[2*q][0] = r4[0]; bb[2*q][1] = r4[1];
                bb[2*q+1][0] = r4[2]; bb[2*q+1][1] = r4[3];
            }
#pragma unroll
            for (int i = 0; i < 2; i++)
#pragma unroll
                for (int j = 0; j < 8; j++) mma16816(acc[i][j], ah[i], bb[j]);
        }
        if (kt + 1 < NK) stsB(kt + 1, st ^ 1);
    }

    // fused epilogue: f tile [256 e][64 s] in smem -> per-s normalize -> per-e sum
    __syncthreads();
    float* smf = (float*)sm;
#pragma unroll
    for (int i = 0; i < 2; i++) {
        int m0 = wid * 32 + i * 16 + (lane >> 2);
#pragma unroll
        for (int j = 0; j < 8; j++) {
            int n0 = j * 8 + (lane & 3) * 2;
            *(float2*)&smf[m0 * SMF2_PAD + n0]       = make_float2(acc[i][j][0], acc[i][j][1]);
            *(float2*)&smf[(m0 + 8) * SMF2_PAD + n0] = make_float2(acc[i][j][2], acc[i][j][3]);
        }
    }
    __syncthreads();
    // per-s sq-norm partials: thread t -> s = t&63, quarter q = t>>6 (64 e each)
    {
        int s = tid & 63, qt = tid >> 6;
        float sq = 0.f;
#pragma unroll 8
        for (int e = 0; e < 64; e++) {
            float v = smf[(qt * 64 + e) * SMF2_PAD + s];
            sq = fmaf(v, v, sq);
        }
        smf[EPI2_RED + qt * 64 + s] = sq;
    }
    __syncthreads();
    if (tid < 64) {
        float tot = smf[EPI2_RED + tid] + smf[EPI2_RED + 64 + tid]
                  + smf[EPI2_RED + 128 + tid] + smf[EPI2_RED + 192 + tid];
        smf[EPI2_INV + tid] = 1.f / fmaxf(sqrtf(tot), NORM_EPS);
    }
    __syncthreads();
    // per-e sum over this CTA's 64 s
    {
        float s = 0.f;
        const float* row = &smf[tid * SMF2_PAD];
        const float* inv = &smf[EPI2_INV];
#pragma unroll 8
        for (int i = 0; i < 64; i++) s = fmaf(row[i], inv[i], s);
        g_part[((size_t)b * 16 + blockIdx.x) * D2 + tid] = s;
    }
}

// ================= reduce / sim =================
__global__ __launch_bounds__(256) void reduce_g_kernel()
{
    int i = blockIdx.x * 256 + threadIdx.x;
    int b = i >> 8, e = i & 255;
    float s = 0.f;
#pragma unroll
    for (int c = 0; c < 16; c++) s += g_part[((size_t)b * 16 + c) * D2 + e];
    g_g[i] = s;
}

__global__ __launch_bounds__(256) void sim_kernel(const float* __restrict__ P, float* __restrict__ out)
{
    const int n = blockIdx.x;
    const int tid = threadIdx.x;
    const int lane = tid & 31, w = tid >> 5;

    __shared__ float gs[BATCH * D2];
    for (int i = tid; i < BATCH * D2; i += 256) gs[i] = g_g[i];

    float pv = P[(size_t)n * D2 + tid];
    float sq = pv * pv;
#pragma unroll
    for (int o = 16; o; o >>= 1) sq += __shfl_xor_sync(0xffffffffu, sq, o);
    __shared__ float red[8];
    if (lane == 0) red[w] = sq;
    __syncthreads();
    float tot = red[0] + red[1] + red[2] + red[3] + red[4] + red[5] + red[6] + red[7];
    float invp = 1.f / fmaxf(sqrtf(tot), NORM_EPS);

    __shared__ float ps[D2];
    ps[tid] = pv * invp;
    __syncthreads();

#pragma unroll
    for (int bi = 0; bi < 4; bi++) {
        int b = w + bi * 8;
        float s = 0.f;
#pragma unroll
        for (int e = lane; e < D2; e += 32) s = fmaf(gs[b * D2 + e], ps[e], s);
#pragma unroll
        for (int o = 16; o; o >>= 1) s += __shfl_xor_sync(0xffffffffu, s, o);
        if (lane == 0) out[b * NC + n] = s;
    }
}

// ---------------- launch ----------------
extern "C" void kernel_launch(void* const* d_in, const int* in_sizes, int n_in,
                              void* d_out, int out_size)
{
    const float* x     = (const float*)d_in[0];
    const float* w1    = (const float*)d_in[1];
    const float* gamma = (const float*)d_in[2];
    const float* beta  = (const float*)d_in[3];
    const float* w2    = (const float*)d_in[4];
    const float* prot  = (const float*)d_in[5];
    float* out = (float*)d_out;

    __nv_bfloat16 *xh, *w1b, *w2hi, *w2lo, *hhi, *hlo;
    cudaGetSymbolAddress((void**)&xh, g_xh);
    cudaGetSymbolAddress((void**)&w1b, g_w1);
    cudaGetSymbolAddress((void**)&w2hi, g_w2hi);
    cudaGetSymbolAddress((void**)&w2lo, g_w2lo);
    cudaGetSymbolAddress((void**)&hhi, g_hhi);
    cudaGetSymbolAddress((void**)&hlo, g_hlo);

    cudaFuncSetAttribute(gemm1_mma, cudaFuncAttributeMaxDynamicSharedMemorySize, G1_SMEM);
    cudaFuncSetAttribute(gemm2_mma, cudaFuncAttributeMaxDynamicSharedMemorySize, G2_SMEM);

    convert_w1_kernel<<<(D1 * C1 + 255) / 256, 256>>>(w1, w1b, D1 * C1);
    convert_w_kernel<<<(D2 * D1 + 255) / 256, 256>>>(w2, w2hi, w2lo, D2 * D1);

    dim3 gx(HW / 32, C1 / 64, BATCH);
    convert_x_kernel<<<gx, 256>>>(x, xh);

    dim3 g1(HW / 128, D1 / 128, BATCH);   // (8,8,32)
    gemm1_mma<<<g1, 256, G1_SMEM>>>(w1b, xh, hhi, hlo);

    bn_reduce_kernel<<<D1 / 256, 256>>>(gamma, beta);

    dim3 g2(HW / 64, 1, BATCH);           // (16,1,32)
    gemm2_mma<<<g2, 256, G2_SMEM>>>(w2hi, w2lo, hhi, hlo);

    reduce_g_kernel<<<32, 256>>>();

    sim_kernel<<<NC, 256>>>(prot, out);
}

// round 16
// speedup vs baseline: 1.0477x; 1.0477x over previous
#include <cuda_runtime.h>
#include <cuda_bf16.h>
#include <math.h>
#include <stdint.h>

// ---------------- problem constants ----------------
#define BATCH 32
#define C1    2048
#define HW    1024
#define D1    1024
#define D2    256
#define NC    1000
#define BN_EPS 1e-5f
#define NORM_EPS 1e-12f

// ---------------- scratch ----------------
__device__ __nv_bfloat16 g_xh[(size_t)BATCH * HW * C1];  // xT bf16 [b,s,c]
__device__ __nv_bfloat16 g_w1[(size_t)D1 * C1];
__device__ __nv_bfloat16 g_w2hi[(size_t)D2 * D1];
__device__ __nv_bfloat16 g_w2lo[(size_t)D2 * D1];
__device__ __nv_bfloat16 g_hhi[(size_t)BATCH * HW * D1]; // hT bf16 hi [b,s,d]
__device__ __nv_bfloat16 g_hlo[(size_t)BATCH * HW * D1];
__device__ float g_bnsum[256 * D1];
__device__ float g_bnsq[256 * D1];
__device__ float g_scale[D1];
__device__ float g_shift[D1];
__device__ float g_part[BATCH * 16 * D2];
__device__ float g_g[BATCH * D2];

// ---------------- low-level helpers ----------------
__device__ __forceinline__ uint32_t smem_u32(const void* p) {
    uint32_t a;
    asm("{ .reg .u64 t; cvta.to.shared.u64 t, %1; cvt.u32.u64 %0, t; }" : "=r"(a) : "l"(p));
    return a;
}
__device__ __forceinline__ void cpa16(uint32_t dst, const void* src) {
    asm volatile("cp.async.cg.shared.global [%0], [%1], 16;" :: "r"(dst), "l"(src));
}
#define CP_COMMIT() asm volatile("cp.async.commit_group;" ::: "memory")
#define CP_WAIT(n)  asm volatile("cp.async.wait_group %0;" :: "n"(n) : "memory")

__device__ __forceinline__ void ldsm4(uint32_t r[4], uint32_t a) {
    asm volatile("ldmatrix.sync.aligned.m8n8.x4.shared.b16 {%0,%1,%2,%3}, [%4];"
        : "=r"(r[0]), "=r"(r[1]), "=r"(r[2]), "=r"(r[3]) : "r"(a));
}
__device__ __forceinline__ void mma16816(float c[4], const uint32_t a[4], const uint32_t b[2]) {
    asm("mma.sync.aligned.m16n8k16.row.col.f32.bf16.bf16.f32 "
        "{%0,%1,%2,%3}, {%4,%5,%6,%7}, {%8,%9}, {%0,%1,%2,%3};"
        : "+f"(c[0]), "+f"(c[1]), "+f"(c[2]), "+f"(c[3])
        : "r"(a[0]), "r"(a[1]), "r"(a[2]), "r"(a[3]), "r"(b[0]), "r"(b[1]));
}
__device__ __forceinline__ float2 bf2f(uint32_t u) {
    return __bfloat1622float2(*reinterpret_cast<const __nv_bfloat162*>(&u));
}

// ---------------- tiling constants ----------------
// gemm1: KT=32, 80B padded rows, 3 stages (wait-1 pipeline)
#define ROWB   80
#define TILE_B (128 * ROWB)         // 10240
#define STAGE1_B (2 * TILE_B)       // 20480 (A, B)
#define G1_SMEM  69632              // 3 stages = 61440; epilogue needs 68608
#define EPI_SUM   16640
#define EPI_SQ    16896
// gemm2: CTA 256(M) x 64(N), fused epilogue
#define A2_TILE (256 * ROWB)        // 20480 per array
#define B2_TILE (64 * ROWB)         // 5120 per array
#define STAGE2_B (2 * A2_TILE + 2 * B2_TILE)   // 51200
#define G2_SMEM (2 * STAGE2_B)      // 102400
#define SMF2_PAD 66                 // even -> float2 aligned
#define EPI2_RED (256 * SMF2_PAD)
#define EPI2_INV (EPI2_RED + 256)

// ================= convert kernels =================
__global__ __launch_bounds__(256) void convert_w1_kernel(
    const float* __restrict__ W, __nv_bfloat16* __restrict__ O, int n)
{
    int i = blockIdx.x * 256 + threadIdx.x;
    if (i < n) O[i] = __float2bfloat16(W[i]);
}

__global__ __launch_bounds__(256) void convert_w_kernel(
    const float* __restrict__ W, __nv_bfloat16* __restrict__ hi, __nv_bfloat16* __restrict__ lo, int n)
{
    int i = blockIdx.x * 256 + threadIdx.x;
    if (i < n) {
        float v = W[i];
        __nv_bfloat16 h = __float2bfloat16(v);
        hi[i] = h;
        lo[i] = __float2bfloat16(v - __bfloat162float(h));
    }
}

__global__ __launch_bounds__(256) void convert_x_kernel(
    const float* __restrict__ X, __nv_bfloat16* __restrict__ T)
{
    __shared__ float t[64][33];
    const int s0 = blockIdx.x * 32, c0 = blockIdx.y * 64, b = blockIdx.z;
    const float* xb = X + (size_t)b * C1 * HW;
#pragma unroll
    for (int it = 0; it < 8; it++) {
        int e = threadIdx.x + it * 256;
        int ci = e >> 5, sj = e & 31;
        t[ci][sj] = xb[(size_t)(c0 + ci) * HW + s0 + sj];
    }
    __syncthreads();
#pragma unroll
    for (int it = 0; it < 8; it++) {
        int e = threadIdx.x + it * 256;
        int sj = e >> 6, ci = e & 63;
        T[((size_t)b * HW + s0 + sj) * C1 + c0 + ci] = __float2bfloat16(t[ci][sj]);
    }
}

// ================= GEMM1: bf16 1-pass, KT=32, 3-stage wait-1 pipeline =================
__global__ __launch_bounds__(256, 2) void gemm1_mma(
    const __nv_bfloat16* __restrict__ A, const __nv_bfloat16* __restrict__ B,
    __nv_bfloat16* __restrict__ Hhi, __nv_bfloat16* __restrict__ Hlo)
{
    extern __shared__ char sm[];
    const uint32_t sb = smem_u32(sm);
    const int tid = threadIdx.x;
    const int lane = tid & 31, wid = tid >> 5;
    const int wm = wid & 3, wn = wid >> 2;
    const int b = blockIdx.z;
    const int tileM = blockIdx.y * 128;
    const int tileN = blockIdx.x * 128;

    const __nv_bfloat16* gA = A + (size_t)tileM * C1;
    const __nv_bfloat16* gB = B + ((size_t)b * HW + tileN) * C1;

    float acc[2][8][4];
#pragma unroll
    for (int i = 0; i < 2; i++)
#pragma unroll
        for (int j = 0; j < 8; j++)
#pragma unroll
            for (int q = 0; q < 4; q++) acc[i][j][q] = 0.f;

    const int lr = tid & 127;
    const int jbase = tid >> 7;
    const int a_row = wm * 32 + (lane & 15);
    const int a_k8  = (lane >> 4) << 3;
    const int b_row = wn * 64 + ((lane >> 4) << 3) + (lane & 7);
    const int b_k8  = ((lane >> 3) & 1) << 3;

    auto issue_stage = [&](int kt, int st) {
        const int k0 = kt * 32;
        const uint32_t s0 = sb + st * STAGE1_B;
#pragma unroll
        for (int it = 0; it < 2; it++) {
            int j = it * 2 + jbase;
            cpa16(s0 + lr * ROWB + j * 16,          gA + (size_t)lr * C1 + k0 + j * 8);
            cpa16(s0 + TILE_B + lr * ROWB + j * 16, gB + (size_t)lr * C1 + k0 + j * 8);
        }
        CP_COMMIT();
    };

    const int NK = C1 / 32;   // 64
    issue_stage(0, 0);
    issue_stage(1, 1);
    for (int kt = 0; kt < NK; kt++) {
        const int st = kt % 3;
        if (kt + 1 < NK) CP_WAIT(1); else CP_WAIT(0);
        __syncthreads();
        if (kt + 2 < NK) issue_stage(kt + 2, (kt + 2) % 3);
        const uint32_t aS = sb + st * STAGE1_B;
        const uint32_t bS = aS + TILE_B;
#pragma unroll
        for (int kk = 0; kk < 2; kk++) {
            const int akb = (kk * 16 + a_k8) * 2;
            const int bkb = (kk * 16 + b_k8) * 2;
            uint32_t a[2][4], bb[8][2];
#pragma unroll
            for (int i = 0; i < 2; i++)
                ldsm4(a[i], aS + (a_row + i * 16) * ROWB + akb);
#pragma unroll
            for (int q = 0; q < 4; q++) {
                uint32_t r4[4];
                ldsm4(r4, bS + (b_row + q * 16) * ROWB + bkb);
                bb[2*q][0] = r4[0]; bb[2*q][1] = r4[1];
                bb[2*q+1][0] = r4[2]; bb[2*q+1][1] = r4[3];
            }
#pragma unroll
            for (int i = 0; i < 2; i++)
#pragma unroll
                for (int j = 0; j < 8; j++) mma16816(acc[i][j], a[i], bb[j]);
        }
    }

    // epilogue: acc -> smem fp32 (pad 130)
    __syncthreads();
    float* smf = (float*)sm;
#pragma unroll
    for (int i = 0; i < 2; i++) {
        int m0 = wm * 32 + i * 16 + (lane >> 2);
#pragma unroll
        for (int j = 0; j < 8; j++) {
            int n0 = wn * 64 + j * 8 + (lane & 3) * 2;
            *(float2*)&smf[m0 * 130 + n0]       = make_float2(acc[i][j][0], acc[i][j][1]);
            *(float2*)&smf[(m0 + 8) * 130 + n0] = make_float2(acc[i][j][2], acc[i][j][3]);
        }
    }
    __syncthreads();

    // (a) transposed bf16 hi/lo out [b,s,d]
    {
        int s = tid & 127, half = tid >> 7;
        __nv_bfloat16* oh = Hhi + ((size_t)b * HW + tileN + s) * D1 + tileM + half * 64;
        __nv_bfloat16* ol = Hlo + ((size_t)b * HW + tileN + s) * D1 + tileM + half * 64;
#pragma unroll
        for (int c = 0; c < 8; c++) {
            __align__(16) __nv_bfloat16 ph[8], pl[8];
#pragma unroll
            for (int e = 0; e < 8; e++) {
                float v = smf[(half * 64 + c * 8 + e) * 130 + s];
                __nv_bfloat16 h = __float2bfloat16(v);
                ph[e] = h;
                pl[e] = __float2bfloat16(v - __bfloat162float(h));
            }
            *(uint4*)(oh + c * 8) = *(const uint4*)ph;
            *(uint4*)(ol + c * 8) = *(const uint4*)pl;
        }
    }

    // (b) fused BN partial stats
    {
        int dl = tid & 127, half = tid >> 7;
        float s = 0.f, q = 0.f;
        const float* row = &smf[dl * 130 + half * 64];
#pragma unroll 8
        for (int i = 0; i < 64; i++) {
            float v = row[i];
            s += v;
            q = fmaf(v, v, q);
        }
        smf[EPI_SUM + tid] = s;
        smf[EPI_SQ + tid]  = q;
        __syncthreads();
        if (half == 0) {
            float S = smf[EPI_SUM + dl] + smf[EPI_SUM + 128 + dl];
            float Q = smf[EPI_SQ + dl]  + smf[EPI_SQ + 128 + dl];
            int p = b * 8 + blockIdx.x;
            g_bnsum[p * D1 + tileM + dl] = S;
            g_bnsq[p * D1 + tileM + dl]  = Q;
        }
    }
}

// ================= BN reduce =================
__global__ __launch_bounds__(256) void bn_reduce_kernel(
    const float* __restrict__ gamma, const float* __restrict__ beta)
{
    int d = blockIdx.x * 256 + threadIdx.x;
    float s = 0.f, q = 0.f;
    for (int p = 0; p < 256; p++) { s += g_bnsum[p * D1 + d]; q += g_bnsq[p * D1 + d]; }
    const float invN = 1.f / (float)(BATCH * HW);
    float mean = s * invN;
    float var = fmaf(-mean, mean, q * invN);
    float sc = gamma[d] * rsqrtf(var + BN_EPS);
    g_scale[d] = sc;
    g_shift[d] = fmaf(-mean, sc, beta[d]);
}

// ================= GEMM2: CTA 256x64, bf16 3-pass, fused BN+ReLU, fused norm+sum =================
__global__ __launch_bounds__(256, 2) void gemm2_mma(
    const __nv_bfloat16* __restrict__ Ahi, const __nv_bfloat16* __restrict__ Alo,
    const __nv_bfloat16* __restrict__ Hhi, const __nv_bfloat16* __restrict__ Hlo)
{
    extern __shared__ char sm[];
    const uint32_t sb = smem_u32(sm);
    const int tid = threadIdx.x;
    const int lane = tid & 31, wid = tid >> 5;
    const int b = blockIdx.z;
    const int tileN = blockIdx.x * 64;

    float acc[2][8][4];
#pragma unroll
    for (int i = 0; i < 2; i++)
#pragma unroll
        for (int j = 0; j < 8; j++)
#pragma unroll
            for (int q = 0; q < 4; q++) acc[i][j][q] = 0.f;

    const int lrA = tid;
    const int lrB = tid & 63;
    const int jB  = tid >> 6;
    const int a_row = wid * 32 + (lane & 15);
    const int a_k8  = (lane >> 4) << 3;
    const int b_row = ((lane >> 4) << 3) + (lane & 7);
    const int b_k8  = ((lane >> 3) & 1) << 3;

    uint4 rh, rl;

    auto issueA = [&](int kt, int st) {
        const int k0 = kt * 32;
        const uint32_t s0 = sb + st * STAGE2_B;
#pragma unroll
        for (int j = 0; j < 4; j++) {
            cpa16(s0 + lrA * ROWB + j * 16,           Ahi + (size_t)lrA * D1 + k0 + j * 8);
            cpa16(s0 + A2_TILE + lrA * ROWB + j * 16, Alo + (size_t)lrA * D1 + k0 + j * 8);
        }
        CP_COMMIT();
    };
    auto ldgB = [&](int kt) {
        const int k0 = kt * 32;
        size_t off = ((size_t)b * HW + tileN + lrB) * D1 + k0 + jB * 8;
        rh = *(const uint4*)(Hhi + off);
        rl = *(const uint4*)(Hlo + off);
    };
    auto stsB = [&](int kt, int st) {
        const int k0 = kt * 32;
        const uint32_t soff = st * STAGE2_B + 2 * A2_TILE;
        int d0 = k0 + jB * 8;
        float sc[8], sh[8];
        *(float4*)&sc[0] = *(const float4*)&g_scale[d0];
        *(float4*)&sc[4] = *(const float4*)&g_scale[d0 + 4];
        *(float4*)&sh[0] = *(const float4*)&g_shift[d0];
        *(float4*)&sh[4] = *(const float4*)&g_shift[d0 + 4];
        const uint32_t* ph = (const uint32_t*)&rh;
        const uint32_t* pl = (const uint32_t*)&rl;
        __align__(16) __nv_bfloat16 bh[8], bl[8];
#pragma unroll
        for (int w = 0; w < 4; w++) {
            float2 fh = bf2f(ph[w]);
            float2 fl = bf2f(pl[w]);
            float v0 = fh.x + fl.x, v1 = fh.y + fl.y;
            float u0 = fmaxf(fmaf(v0, sc[2*w],   sh[2*w]),   0.f);
            float u1 = fmaxf(fmaf(v1, sc[2*w+1], sh[2*w+1]), 0.f);
            __nv_bfloat16 h0 = __float2bfloat16(u0);
            __nv_bfloat16 h1 = __float2bfloat16(u1);
            bh[2*w] = h0;   bl[2*w]   = __float2bfloat16(u0 - __bfloat162float(h0));
            bh[2*w+1] = h1; bl[2*w+1] = __float2bfloat16(u1 - __bfloat162float(h1));
        }
        *(uint4*)(sm + soff + lrB * ROWB + jB * 16)           = *(const uint4*)bh;
        *(uint4*)(sm + soff + B2_TILE + lrB * ROWB + jB * 16) = *(const uint4*)bl;
    };

    const int NK = D1 / 32;   // 32
    issueA(0, 0);
    ldgB(0);
    stsB(0, 0);
    for (int kt = 0; kt < NK; kt++) {
        const int st = kt & 1;
        CP_WAIT(0);
        __syncthreads();
        if (kt + 1 < NK) { issueA(kt + 1, st ^ 1); ldgB(kt + 1); }
        const uint32_t s0 = sb + st * STAGE2_B;
        const uint32_t aHs = s0, aLs = s0 + A2_TILE;
        const uint32_t bHs = s0 + 2 * A2_TILE, bLs = bHs + B2_TILE;
#pragma unroll
        for (int kk = 0; kk < 2; kk++) {
            const int akb = (kk * 16 + a_k8) * 2;
            const int bkb = (kk * 16 + b_k8) * 2;
            uint32_t ah[2][4], al[2][4], bb[8][2];
#pragma unroll
            for (int i = 0; i < 2; i++)
                ldsm4(ah[i], aHs + (a_row + i * 16) * ROWB + akb);
#pragma unroll
            for (int q = 0; q < 4; q++) {
                uint32_t r4[4];
                ldsm4(r4, bHs + (b_row + q * 16) * ROWB + bkb);
                bb[2*q][0] = r4[0]; bb[2*q][1] = r4[1];
                bb[2*q+1][0] = r4[2]; bb[2*q+1][1] = r4[3];
            }
#pragma unroll
            for (int i = 0; i < 2; i++)
#pragma unroll
                for (int j = 0; j < 8; j++) mma16816(acc[i][j], ah[i], bb[j]);
#pragma unroll
            for (int i = 0; i < 2; i++)
                ldsm4(al[i], aLs + (a_row + i * 16) * ROWB + akb);
#pragma unroll
            for (int i = 0; i < 2; i++)
#pragma unroll
                for (int j = 0; j < 8; j++) mma16816(acc[i][j], al[i], bb[j]);
#pragma unroll
            for (int q = 0; q < 4; q++) {
                uint32_t r4[4];
                ldsm4(r4, bLs + (b_row + q * 16) * ROWB + bkb);
                bb[2*q][0] = r4[0]; bb[2*q][1] = r4[1];
                bb[2*q+1][0] = r4[2]; bb[2*q+1][1] = r4[3];
            }
#pragma unroll
            for (int i = 0; i < 2; i++)
#pragma unroll
                for (int j = 0; j < 8; j++) mma16816(acc[i][j], ah[i], bb[j]);
        }
        if (kt + 1 < NK) stsB(kt + 1, st ^ 1);
    }

    // fused epilogue: f tile [256 e][64 s] -> per-s normalize -> per-e sum
    __syncthreads();
    float* smf = (float*)sm;
#pragma unroll
    for (int i = 0; i < 2; i++) {
        int m0 = wid * 32 + i * 16 + (lane >> 2);
#pragma unroll
        for (int j = 0; j < 8; j++) {
            int n0 = j * 8 + (lane & 3) * 2;
            *(float2*)&smf[m0 * SMF2_PAD + n0]       = make_float2(acc[i][j][0], acc[i][j][1]);
            *(float2*)&smf[(m0 + 8) * SMF2_PAD + n0] = make_float2(acc[i][j][2], acc[i][j][3]);
        }
    }
    __syncthreads();
    {
        int s = tid & 63, qt = tid >> 6;
        float sq = 0.f;
#pragma unroll 8
        for (int e = 0; e < 64; e++) {
            float v = smf[(qt * 64 + e) * SMF2_PAD + s];
            sq = fmaf(v, v, sq);
        }
        smf[EPI2_RED + qt * 64 + s] = sq;
    }
    __syncthreads();
    if (tid < 64) {
        float tot = smf[EPI2_RED + tid] + smf[EPI2_RED + 64 + tid]
                  + smf[EPI2_RED + 128 + tid] + smf[EPI2_RED + 192 + tid];
        smf[EPI2_INV + tid] = 1.f / fmaxf(sqrtf(tot), NORM_EPS);
    }
    __syncthreads();
    {
        float s = 0.f;
        const float* row = &smf[tid * SMF2_PAD];
        const float* inv = &smf[EPI2_INV];
#pragma unroll 8
        for (int i = 0; i < 64; i++) s = fmaf(row[i], inv[i], s);
        g_part[((size_t)b * 16 + blockIdx.x) * D2 + tid] = s;
    }
}

// ================= reduce / sim =================
__global__ __launch_bounds__(256) void reduce_g_kernel()
{
    int i = blockIdx.x * 256 + threadIdx.x;
    int b = i >> 8, e = i & 255;
    float s = 0.f;
#pragma unroll
    for (int c = 0; c < 16; c++) s += g_part[((size_t)b * 16 + c) * D2 + e];
    g_g[i] = s;
}

__global__ __launch_bounds__(256) void sim_kernel(const float* __restrict__ P, float* __restrict__ out)
{
    const int n = blockIdx.x;
    const int tid = threadIdx.x;
    const int lane = tid & 31, w = tid >> 5;

    __shared__ float gs[BATCH * D2];
    for (int i = tid; i < BATCH * D2; i += 256) gs[i] = g_g[i];

    float pv = P[(size_t)n * D2 + tid];
    float sq = pv * pv;
#pragma unroll
    for (int o = 16; o; o >>= 1) sq += __shfl_xor_sync(0xffffffffu, sq, o);
    __shared__ float red[8];
    if (lane == 0) red[w] = sq;
    __syncthreads();
    float tot = red[0] + red[1] + red[2] + red[3] + red[4] + red[5] + red[6] + red[7];
    float invp = 1.f / fmaxf(sqrtf(tot), NORM_EPS);

    __shared__ float ps[D2];
    ps[tid] = pv * invp;
    __syncthreads();

#pragma unroll
    for (int bi = 0; bi < 4; bi++) {
        int b = w + bi * 8;
        float s = 0.f;
#pragma unroll
        for (int e = lane; e < D2; e += 32) s = fmaf(gs[b * D2 + e], ps[e], s);
#pragma unroll
        for (int o = 16; o; o >>= 1) s += __shfl_xor_sync(0xffffffffu, s, o);
        if (lane == 0) out[b * NC + n] = s;
    }
}

// ---------------- launch ----------------
extern "C" void kernel_launch(void* const* d_in, const int* in_sizes, int n_in,
                              void* d_out, int out_size)
{
    const float* x     = (const float*)d_in[0];
    const float* w1    = (const float*)d_in[1];
    const float* gamma = (const float*)d_in[2];
    const float* beta  = (const float*)d_in[3];
    const float* w2    = (const float*)d_in[4];
    const float* prot  = (const float*)d_in[5];
    float* out = (float*)d_out;

    __nv_bfloat16 *xh, *w1b, *w2hi, *w2lo, *hhi, *hlo;
    cudaGetSymbolAddress((void**)&xh, g_xh);
    cudaGetSymbolAddress((void**)&w1b, g_w1);
    cudaGetSymbolAddress((void**)&w2hi, g_w2hi);
    cudaGetSymbolAddress((void**)&w2lo, g_w2lo);
    cudaGetSymbolAddress((void**)&hhi, g_hhi);
    cudaGetSymbolAddress((void**)&hlo, g_hlo);

    cudaFuncSetAttribute(gemm1_mma, cudaFuncAttributeMaxDynamicSharedMemorySize, G1_SMEM);
    cudaFuncSetAttribute(gemm2_mma, cudaFuncAttributeMaxDynamicSharedMemorySize, G2_SMEM);

    convert_w1_kernel<<<(D1 * C1 + 255) / 256, 256>>>(w1, w1b, D1 * C1);
    convert_w_kernel<<<(D2 * D1 + 255) / 256, 256>>>(w2, w2hi, w2lo, D2 * D1);

    dim3 gx(HW / 32, C1 / 64, BATCH);
    convert_x_kernel<<<gx, 256>>>(x, xh);

    dim3 g1(HW / 128, D1 / 128, BATCH);   // (8,8,32)
    gemm1_mma<<<g1, 256, G1_SMEM>>>(w1b, xh, hhi, hlo);

    bn_reduce_kernel<<<D1 / 256, 256>>>(gamma, beta);

    dim3 g2(HW / 64, 1, BATCH);           // (16,1,32)
    gemm2_mma<<<g2, 256, G2_SMEM>>>(w2hi, w2lo, hhi, hlo);

    reduce_g_kernel<<<32, 256>>>();

    sim_kernel<<<NC, 256>>>(prot, out);
}